// round 1
// baseline (speedup 1.0000x reference)
#include <cuda_runtime.h>
#include <cuda_bf16.h>
#include <cstdint>

// Problem constants (fixed by reference)
#define N_NODES 50000
#define N_EDGES 800000
#define D_IN    256
#define D_OUT   256

// Scratch for xw = x @ W  (51.2 MB static device global — allowed)
__device__ float g_xw[(size_t)N_NODES * D_OUT];

// ---------------------------------------------------------------------------
// Kernel 1: SGEMM  xw[M,256] = x[M,256] @ W[256,256]
// 64x64 block tile, BK=16, 256 threads, 4x4 per thread.
// ---------------------------------------------------------------------------
#define BM 64
#define BN 64
#define BK 16

__global__ __launch_bounds__(256)
void gemm_xw_kernel(const float* __restrict__ x,
                    const float* __restrict__ W)
{
    __shared__ float As[BK][BM + 4];   // transposed A tile, padded
    __shared__ float Bs[BK][BN];

    const int t  = threadIdx.x;            // 0..255
    const int tx = t % 16;                  // col group
    const int ty = t / 16;                  // row group

    const int row0 = blockIdx.x * BM;       // M tile base
    const int col0 = blockIdx.y * BN;       // N tile base

    float acc[4][4];
    #pragma unroll
    for (int i = 0; i < 4; i++)
        #pragma unroll
        for (int j = 0; j < 4; j++)
            acc[i][j] = 0.f;

    // A-tile load mapping: 256 threads x 1 float4 = 64 rows x 16 k
    const int a_m  = t / 4;          // 0..63
    const int a_k4 = (t % 4) * 4;    // 0,4,8,12
    // B-tile load mapping: 256 threads x 1 float4 = 16 k x 64 n
    const int b_k  = t / 16;         // 0..15
    const int b_n4 = (t % 16) * 4;   // 0..60

    for (int k0 = 0; k0 < D_IN; k0 += BK) {
        // Load A tile (guard M bound)
        float4 av = make_float4(0.f, 0.f, 0.f, 0.f);
        int gm = row0 + a_m;
        if (gm < N_NODES)
            av = *reinterpret_cast<const float4*>(&x[(size_t)gm * D_IN + k0 + a_k4]);
        As[a_k4 + 0][a_m] = av.x;
        As[a_k4 + 1][a_m] = av.y;
        As[a_k4 + 2][a_m] = av.z;
        As[a_k4 + 3][a_m] = av.w;

        // Load B tile (K,N both multiples of tile; no guard needed)
        float4 bv = *reinterpret_cast<const float4*>(&W[(size_t)(k0 + b_k) * D_OUT + col0 + b_n4]);
        Bs[b_k][b_n4 + 0] = bv.x;
        Bs[b_k][b_n4 + 1] = bv.y;
        Bs[b_k][b_n4 + 2] = bv.z;
        Bs[b_k][b_n4 + 3] = bv.w;

        __syncthreads();

        #pragma unroll
        for (int k = 0; k < BK; k++) {
            float a[4], b[4];
            #pragma unroll
            for (int i = 0; i < 4; i++) a[i] = As[k][ty * 4 + i];
            #pragma unroll
            for (int j = 0; j < 4; j++) b[j] = Bs[k][tx * 4 + j];
            #pragma unroll
            for (int i = 0; i < 4; i++)
                #pragma unroll
                for (int j = 0; j < 4; j++)
                    acc[i][j] = fmaf(a[i], b[j], acc[i][j]);
        }
        __syncthreads();
    }

    // Store 4x4 micro-tile (float4 per row)
    #pragma unroll
    for (int i = 0; i < 4; i++) {
        int gm = row0 + ty * 4 + i;
        if (gm < N_NODES) {
            float4 v = make_float4(acc[i][0], acc[i][1], acc[i][2], acc[i][3]);
            *reinterpret_cast<float4*>(&g_xw[(size_t)gm * D_OUT + col0 + tx * 4]) = v;
        }
    }
}

// ---------------------------------------------------------------------------
// Kernel 2: COO scatter — one warp per edge.
// out[row] += val * xw[col]  (256 floats, 8 atomicAdds per lane)
// ---------------------------------------------------------------------------
__global__ __launch_bounds__(256)
void scatter_kernel(const int*   __restrict__ edge_row,
                    const int*   __restrict__ edge_col,
                    const float* __restrict__ edge_vals,
                    float*       __restrict__ out)
{
    const int warp_id = (blockIdx.x * blockDim.x + threadIdx.x) >> 5;
    const int lane    = threadIdx.x & 31;
    if (warp_id >= N_EDGES) return;

    const int   r = edge_row[warp_id];
    const int   c = edge_col[warp_id];
    const float v = edge_vals[warp_id];

    const float4* __restrict__ src = reinterpret_cast<const float4*>(&g_xw[(size_t)c * D_OUT]);
    float* __restrict__ dst = out + (size_t)r * D_OUT;

    #pragma unroll
    for (int i = 0; i < 2; i++) {
        float4 m = src[lane + 32 * i];
        int base = (lane + 32 * i) * 4;
        atomicAdd(dst + base + 0, v * m.x);
        atomicAdd(dst + base + 1, v * m.y);
        atomicAdd(dst + base + 2, v * m.z);
        atomicAdd(dst + base + 3, v * m.w);
    }
}

// ---------------------------------------------------------------------------
// Kernel 3: epilogue  out = relu(out + bias)
// ---------------------------------------------------------------------------
__global__ __launch_bounds__(256)
void epilogue_kernel(float* __restrict__ out,
                     const float* __restrict__ bias)
{
    const size_t total4 = (size_t)N_NODES * D_OUT / 4;
    size_t idx = (size_t)blockIdx.x * blockDim.x + threadIdx.x;
    if (idx >= total4) return;

    int col4 = (int)((idx * 4) % D_OUT);
    float4 b = *reinterpret_cast<const float4*>(&bias[col4]);
    float4 v = reinterpret_cast<float4*>(out)[idx];
    v.x = fmaxf(v.x + b.x, 0.f);
    v.y = fmaxf(v.y + b.y, 0.f);
    v.z = fmaxf(v.z + b.z, 0.f);
    v.w = fmaxf(v.w + b.w, 0.f);
    reinterpret_cast<float4*>(out)[idx] = v;
}

// ---------------------------------------------------------------------------
// Launch
// ---------------------------------------------------------------------------
extern "C" void kernel_launch(void* const* d_in, const int* in_sizes, int n_in,
                              void* d_out, int out_size)
{
    const float* x         = (const float*)d_in[0];
    const int*   edge_row  = (const int*)  d_in[1];
    const int*   edge_col  = (const int*)  d_in[2];
    const float* edge_vals = (const float*)d_in[3];
    const float* weight    = (const float*)d_in[4];
    const float* bias      = (const float*)d_in[5];
    float* out = (float*)d_out;

    // 1) xw = x @ W
    dim3 gemm_grid((N_NODES + BM - 1) / BM, D_OUT / BN);
    gemm_xw_kernel<<<gemm_grid, 256>>>(x, weight);

    // 2) zero the accumulator (d_out is poisoned before timing)
    cudaMemsetAsync(d_out, 0, (size_t)N_NODES * D_OUT * sizeof(float), 0);

    // 3) edge scatter, one warp per edge (8 warps / block)
    int n_warps  = N_EDGES;
    int n_blocks = (n_warps + 7) / 8;
    scatter_kernel<<<n_blocks, 256>>>(edge_row, edge_col, edge_vals, out);

    // 4) bias + relu
    size_t total4 = (size_t)N_NODES * D_OUT / 4;
    epilogue_kernel<<<(int)((total4 + 255) / 256), 256>>>(out, bias);
}

// round 2
// speedup vs baseline: 2.2091x; 2.2091x over previous
#include <cuda_runtime.h>
#include <cuda_bf16.h>
#include <cstdint>

#define N_NODES 50000
#define N_EDGES 800000
#define D_IN    256
#define D_OUT   256

// ---------------- static device scratch (no allocations) -------------------
__device__ float g_xw[(size_t)N_NODES * D_OUT];   // 51.2 MB
__device__ int   g_deg[N_NODES];                  // per-row degree
__device__ int   g_fill[N_NODES];                 // fill cursors
__device__ int   g_rowptr[N_NODES + 1];           // CSR row pointers
__device__ int   g_ecol[N_EDGES];                 // CSR col indices
__device__ float g_eval[N_EDGES];                 // CSR edge values

// ---------------------------------------------------------------------------
// GEMM: xw[M,256] = x[M,256] @ W[256,256]
// 128x128 block tile, BK=8, 256 threads, 8x8 per thread (split 4+4 micro-rows)
// ---------------------------------------------------------------------------
#define GBM 128
#define GBN 128
#define GBK 8

__global__ __launch_bounds__(256)
void gemm_xw_kernel(const float* __restrict__ x,
                    const float* __restrict__ W)
{
    __shared__ float As[GBK][GBM];
    __shared__ float Bs[GBK][GBN];

    const int t    = threadIdx.x;
    const int row0 = blockIdx.x * GBM;
    const int col0 = blockIdx.y * GBN;

    // A-tile loads: 128 rows x 8 k = 256 float4 (one per thread)
    const int a_m = t >> 1;
    const int a_k = (t & 1) * 4;
    // B-tile loads: 8 k x 128 n = 256 float4
    const int b_k = t >> 5;
    const int b_n = (t & 31) * 4;

    const int tx = t & 15;   // 0..15 -> 8 cols (tx*4, tx*4+64)
    const int ty = t >> 4;   // 0..15 -> 8 rows (ty*4, ty*4+64)

    float acc[8][8];
    #pragma unroll
    for (int i = 0; i < 8; i++)
        #pragma unroll
        for (int j = 0; j < 8; j++) acc[i][j] = 0.f;

    for (int k0 = 0; k0 < D_IN; k0 += GBK) {
        float4 av = make_float4(0.f, 0.f, 0.f, 0.f);
        const int gm = row0 + a_m;
        if (gm < N_NODES)
            av = *reinterpret_cast<const float4*>(&x[(size_t)gm * D_IN + k0 + a_k]);
        As[a_k + 0][a_m] = av.x;
        As[a_k + 1][a_m] = av.y;
        As[a_k + 2][a_m] = av.z;
        As[a_k + 3][a_m] = av.w;

        const float4 bv = *reinterpret_cast<const float4*>(
            &W[(size_t)(k0 + b_k) * D_OUT + col0 + b_n]);
        *reinterpret_cast<float4*>(&Bs[b_k][b_n]) = bv;

        __syncthreads();

        #pragma unroll
        for (int k = 0; k < GBK; k++) {
            float a[8], b[8];
            *reinterpret_cast<float4*>(&a[0]) = *reinterpret_cast<const float4*>(&As[k][ty * 4]);
            *reinterpret_cast<float4*>(&a[4]) = *reinterpret_cast<const float4*>(&As[k][ty * 4 + 64]);
            *reinterpret_cast<float4*>(&b[0]) = *reinterpret_cast<const float4*>(&Bs[k][tx * 4]);
            *reinterpret_cast<float4*>(&b[4]) = *reinterpret_cast<const float4*>(&Bs[k][tx * 4 + 64]);
            #pragma unroll
            for (int i = 0; i < 8; i++)
                #pragma unroll
                for (int j = 0; j < 8; j++)
                    acc[i][j] = fmaf(a[i], b[j], acc[i][j]);
        }
        __syncthreads();
    }

    #pragma unroll
    for (int i = 0; i < 8; i++) {
        const int gm = row0 + ty * 4 + ((i < 4) ? i : (64 + i - 4));
        if (gm < N_NODES) {
            float* dst = &g_xw[(size_t)gm * D_OUT + col0];
            *reinterpret_cast<float4*>(dst + tx * 4) =
                make_float4(acc[i][0], acc[i][1], acc[i][2], acc[i][3]);
            *reinterpret_cast<float4*>(dst + tx * 4 + 64) =
                make_float4(acc[i][4], acc[i][5], acc[i][6], acc[i][7]);
        }
    }
}

// ---------------------------------------------------------------------------
// CSR construction
// ---------------------------------------------------------------------------
__global__ __launch_bounds__(256)
void zero_counts_kernel()
{
    int i = blockIdx.x * blockDim.x + threadIdx.x;
    if (i < N_NODES) { g_deg[i] = 0; g_fill[i] = 0; }
}

__global__ __launch_bounds__(256)
void count_kernel(const int* __restrict__ edge_row)
{
    int e = blockIdx.x * blockDim.x + threadIdx.x;
    if (e < N_EDGES) atomicAdd(&g_deg[edge_row[e]], 1);
}

// Single-block exclusive scan of g_deg -> g_rowptr (N=50000)
__global__ __launch_bounds__(1024)
void scan_kernel()
{
    __shared__ int partial[1024];
    const int t = threadIdx.x;
    const int CHUNK = (N_NODES + 1023) / 1024;   // 49
    const int base = t * CHUNK;

    int s = 0;
    for (int i = 0; i < CHUNK; i++) {
        int idx = base + i;
        if (idx < N_NODES) s += g_deg[idx];
    }
    partial[t] = s;
    __syncthreads();

    // Hillis-Steele inclusive scan
    for (int off = 1; off < 1024; off <<= 1) {
        int v = (t >= off) ? partial[t - off] : 0;
        __syncthreads();
        partial[t] += v;
        __syncthreads();
    }

    int run = (t == 0) ? 0 : partial[t - 1];
    for (int i = 0; i < CHUNK; i++) {
        int idx = base + i;
        if (idx < N_NODES) { g_rowptr[idx] = run; run += g_deg[idx]; }
    }
    if (t == 1023) g_rowptr[N_NODES] = partial[1023];
}

__global__ __launch_bounds__(256)
void fill_kernel(const int*   __restrict__ edge_row,
                 const int*   __restrict__ edge_col,
                 const float* __restrict__ edge_vals)
{
    int e = blockIdx.x * blockDim.x + threadIdx.x;
    if (e >= N_EDGES) return;
    const int r = edge_row[e];
    const int p = g_rowptr[r] + atomicAdd(&g_fill[r], 1);
    g_ecol[p] = edge_col[e];
    g_eval[p] = edge_vals[e];
}

// ---------------------------------------------------------------------------
// SpMM (CSR): one warp per row; register accumulation; fused bias + relu.
// ---------------------------------------------------------------------------
__global__ __launch_bounds__(256)
void spmm_kernel(const float* __restrict__ bias,
                 float*       __restrict__ out)
{
    const int warp = (blockIdx.x * blockDim.x + threadIdx.x) >> 5;
    const int lane = threadIdx.x & 31;
    if (warp >= N_NODES) return;

    const int s = g_rowptr[warp];
    const int e = g_rowptr[warp + 1];

    float4 acc0 = make_float4(0.f, 0.f, 0.f, 0.f);
    float4 acc1 = make_float4(0.f, 0.f, 0.f, 0.f);

    int i = s;
    for (; i + 1 < e; i += 2) {
        const int   c0 = g_ecol[i];
        const int   c1 = g_ecol[i + 1];
        const float v0 = g_eval[i];
        const float v1 = g_eval[i + 1];
        const float4* s0 = reinterpret_cast<const float4*>(&g_xw[(size_t)c0 * D_OUT]);
        const float4* s1 = reinterpret_cast<const float4*>(&g_xw[(size_t)c1 * D_OUT]);
        const float4 m00 = s0[lane];
        const float4 m01 = s0[lane + 32];
        const float4 m10 = s1[lane];
        const float4 m11 = s1[lane + 32];
        acc0.x = fmaf(v0, m00.x, fmaf(v1, m10.x, acc0.x));
        acc0.y = fmaf(v0, m00.y, fmaf(v1, m10.y, acc0.y));
        acc0.z = fmaf(v0, m00.z, fmaf(v1, m10.z, acc0.z));
        acc0.w = fmaf(v0, m00.w, fmaf(v1, m10.w, acc0.w));
        acc1.x = fmaf(v0, m01.x, fmaf(v1, m11.x, acc1.x));
        acc1.y = fmaf(v0, m01.y, fmaf(v1, m11.y, acc1.y));
        acc1.z = fmaf(v0, m01.z, fmaf(v1, m11.z, acc1.z));
        acc1.w = fmaf(v0, m01.w, fmaf(v1, m11.w, acc1.w));
    }
    if (i < e) {
        const int   c0 = g_ecol[i];
        const float v0 = g_eval[i];
        const float4* s0 = reinterpret_cast<const float4*>(&g_xw[(size_t)c0 * D_OUT]);
        const float4 m00 = s0[lane];
        const float4 m01 = s0[lane + 32];
        acc0.x = fmaf(v0, m00.x, acc0.x);
        acc0.y = fmaf(v0, m00.y, acc0.y);
        acc0.z = fmaf(v0, m00.z, acc0.z);
        acc0.w = fmaf(v0, m00.w, acc0.w);
        acc1.x = fmaf(v0, m01.x, acc1.x);
        acc1.y = fmaf(v0, m01.y, acc1.y);
        acc1.z = fmaf(v0, m01.z, acc1.z);
        acc1.w = fmaf(v0, m01.w, acc1.w);
    }

    const float4 b0 = reinterpret_cast<const float4*>(bias)[lane];
    const float4 b1 = reinterpret_cast<const float4*>(bias)[lane + 32];
    acc0.x = fmaxf(acc0.x + b0.x, 0.f);
    acc0.y = fmaxf(acc0.y + b0.y, 0.f);
    acc0.z = fmaxf(acc0.z + b0.z, 0.f);
    acc0.w = fmaxf(acc0.w + b0.w, 0.f);
    acc1.x = fmaxf(acc1.x + b1.x, 0.f);
    acc1.y = fmaxf(acc1.y + b1.y, 0.f);
    acc1.z = fmaxf(acc1.z + b1.z, 0.f);
    acc1.w = fmaxf(acc1.w + b1.w, 0.f);

    float4* dst = reinterpret_cast<float4*>(&out[(size_t)warp * D_OUT]);
    dst[lane]      = acc0;
    dst[lane + 32] = acc1;
}

// ---------------------------------------------------------------------------
// Launch
// ---------------------------------------------------------------------------
extern "C" void kernel_launch(void* const* d_in, const int* in_sizes, int n_in,
                              void* d_out, int out_size)
{
    const float* x         = (const float*)d_in[0];
    const int*   edge_row  = (const int*)  d_in[1];
    const int*   edge_col  = (const int*)  d_in[2];
    const float* edge_vals = (const float*)d_in[3];
    const float* weight    = (const float*)d_in[4];
    const float* bias      = (const float*)d_in[5];
    float* out = (float*)d_out;

    // CSR build
    zero_counts_kernel<<<(N_NODES + 255) / 256, 256>>>();
    count_kernel<<<(N_EDGES + 255) / 256, 256>>>(edge_row);
    scan_kernel<<<1, 1024>>>();
    fill_kernel<<<(N_EDGES + 255) / 256, 256>>>(edge_row, edge_col, edge_vals);

    // GEMM
    dim3 gemm_grid((N_NODES + GBM - 1) / GBM, D_OUT / GBN);
    gemm_xw_kernel<<<gemm_grid, 256>>>(x, weight);

    // SpMM + bias + relu (one warp per row)
    int n_blocks = (N_NODES * 32 + 255) / 256;
    spmm_kernel<<<n_blocks, 256>>>(bias, out);
}

// round 3
// speedup vs baseline: 2.5509x; 1.1547x over previous
#include <cuda_runtime.h>
#include <cuda_bf16.h>
#include <cstdint>

#define N_NODES 50000
#define N_EDGES 800000
#define D_IN    256
#define D_OUT   256

// ---------------- static device scratch (no allocations) -------------------
__device__ float g_xw[(size_t)N_NODES * D_OUT];   // 51.2 MB
__device__ int   g_deg[N_NODES];
__device__ int   g_fill[N_NODES];
__device__ int   g_rowptr[N_NODES + 1];
__device__ int2  g_epack[N_EDGES];                // {col, bitcast(val)}

// ---------------------------------------------------------------------------
// GEMM: xw = x @ W   (128x128 tile, BK=8, 8x8 microtile) — at fp32 FMA roofline
// ---------------------------------------------------------------------------
#define GBM 128
#define GBN 128
#define GBK 8

__global__ __launch_bounds__(256)
void gemm_xw_kernel(const float* __restrict__ x,
                    const float* __restrict__ W)
{
    __shared__ float As[GBK][GBM];
    __shared__ float Bs[GBK][GBN];

    const int t    = threadIdx.x;
    const int row0 = blockIdx.x * GBM;
    const int col0 = blockIdx.y * GBN;

    const int a_m = t >> 1;
    const int a_k = (t & 1) * 4;
    const int b_k = t >> 5;
    const int b_n = (t & 31) * 4;

    const int tx = t & 15;
    const int ty = t >> 4;

    float acc[8][8];
    #pragma unroll
    for (int i = 0; i < 8; i++)
        #pragma unroll
        for (int j = 0; j < 8; j++) acc[i][j] = 0.f;

    for (int k0 = 0; k0 < D_IN; k0 += GBK) {
        float4 av = make_float4(0.f, 0.f, 0.f, 0.f);
        const int gm = row0 + a_m;
        if (gm < N_NODES)
            av = *reinterpret_cast<const float4*>(&x[(size_t)gm * D_IN + k0 + a_k]);
        As[a_k + 0][a_m] = av.x;
        As[a_k + 1][a_m] = av.y;
        As[a_k + 2][a_m] = av.z;
        As[a_k + 3][a_m] = av.w;

        const float4 bv = *reinterpret_cast<const float4*>(
            &W[(size_t)(k0 + b_k) * D_OUT + col0 + b_n]);
        *reinterpret_cast<float4*>(&Bs[b_k][b_n]) = bv;

        __syncthreads();

        #pragma unroll
        for (int k = 0; k < GBK; k++) {
            float a[8], b[8];
            *reinterpret_cast<float4*>(&a[0]) = *reinterpret_cast<const float4*>(&As[k][ty * 4]);
            *reinterpret_cast<float4*>(&a[4]) = *reinterpret_cast<const float4*>(&As[k][ty * 4 + 64]);
            *reinterpret_cast<float4*>(&b[0]) = *reinterpret_cast<const float4*>(&Bs[k][tx * 4]);
            *reinterpret_cast<float4*>(&b[4]) = *reinterpret_cast<const float4*>(&Bs[k][tx * 4 + 64]);
            #pragma unroll
            for (int i = 0; i < 8; i++)
                #pragma unroll
                for (int j = 0; j < 8; j++)
                    acc[i][j] = fmaf(a[i], b[j], acc[i][j]);
        }
        __syncthreads();
    }

    #pragma unroll
    for (int i = 0; i < 8; i++) {
        const int gm = row0 + ty * 4 + ((i < 4) ? i : (64 + i - 4));
        if (gm < N_NODES) {
            float* dst = &g_xw[(size_t)gm * D_OUT + col0];
            *reinterpret_cast<float4*>(dst + tx * 4) =
                make_float4(acc[i][0], acc[i][1], acc[i][2], acc[i][3]);
            *reinterpret_cast<float4*>(dst + tx * 4 + 64) =
                make_float4(acc[i][4], acc[i][5], acc[i][6], acc[i][7]);
        }
    }
}

// ---------------------------------------------------------------------------
// CSR construction
// ---------------------------------------------------------------------------
__global__ __launch_bounds__(256)
void zero_counts_kernel()
{
    int i = blockIdx.x * blockDim.x + threadIdx.x;
    if (i < N_NODES) { g_deg[i] = 0; g_fill[i] = 0; }
}

__global__ __launch_bounds__(256)
void count_kernel(const int* __restrict__ edge_row)
{
    int e = blockIdx.x * blockDim.x + threadIdx.x;
    if (e < N_EDGES) atomicAdd(&g_deg[edge_row[e]], 1);
}

__global__ __launch_bounds__(1024)
void scan_kernel()
{
    __shared__ int partial[1024];
    const int t = threadIdx.x;
    const int CHUNK = (N_NODES + 1023) / 1024;
    const int base = t * CHUNK;

    int s = 0;
    for (int i = 0; i < CHUNK; i++) {
        int idx = base + i;
        if (idx < N_NODES) s += g_deg[idx];
    }
    partial[t] = s;
    __syncthreads();

    for (int off = 1; off < 1024; off <<= 1) {
        int v = (t >= off) ? partial[t - off] : 0;
        __syncthreads();
        partial[t] += v;
        __syncthreads();
    }

    int run = (t == 0) ? 0 : partial[t - 1];
    for (int i = 0; i < CHUNK; i++) {
        int idx = base + i;
        if (idx < N_NODES) { g_rowptr[idx] = run; run += g_deg[idx]; }
    }
    if (t == 1023) g_rowptr[N_NODES] = partial[1023];
}

__global__ __launch_bounds__(256)
void fill_kernel(const int*   __restrict__ edge_row,
                 const int*   __restrict__ edge_col,
                 const float* __restrict__ edge_vals)
{
    int e = blockIdx.x * blockDim.x + threadIdx.x;
    if (e >= N_EDGES) return;
    const int r = edge_row[e];
    const int p = g_rowptr[r] + atomicAdd(&g_fill[r], 1);
    g_epack[p] = make_int2(edge_col[e], __float_as_int(edge_vals[e]));
}

// ---------------------------------------------------------------------------
// SpMM (CSR): 2 warps per row (each owns 128 cols), 4-edge unroll,
// fused bias + relu.
// ---------------------------------------------------------------------------
__global__ __launch_bounds__(256)
void spmm_kernel(const float* __restrict__ bias,
                 float*       __restrict__ out)
{
    const int gwarp = (blockIdx.x * blockDim.x + threadIdx.x) >> 5;
    const int row   = gwarp >> 1;
    const int half  = gwarp & 1;
    const int lane  = threadIdx.x & 31;
    if (row >= N_NODES) return;

    const int s = g_rowptr[row];
    const int e = g_rowptr[row + 1];
    const int coff = half * 128 + lane * 4;       // float index within D_OUT

    float4 acc = make_float4(0.f, 0.f, 0.f, 0.f);

    int i = s;
    for (; i + 3 < e; i += 4) {
        const int2 p0 = g_epack[i];
        const int2 p1 = g_epack[i + 1];
        const int2 p2 = g_epack[i + 2];
        const int2 p3 = g_epack[i + 3];
        const float v0 = __int_as_float(p0.y);
        const float v1 = __int_as_float(p1.y);
        const float v2 = __int_as_float(p2.y);
        const float v3 = __int_as_float(p3.y);

        const float4 m0 = __ldg(reinterpret_cast<const float4*>(&g_xw[(size_t)p0.x * D_OUT + coff]));
        const float4 m1 = __ldg(reinterpret_cast<const float4*>(&g_xw[(size_t)p1.x * D_OUT + coff]));
        const float4 m2 = __ldg(reinterpret_cast<const float4*>(&g_xw[(size_t)p2.x * D_OUT + coff]));
        const float4 m3 = __ldg(reinterpret_cast<const float4*>(&g_xw[(size_t)p3.x * D_OUT + coff]));

        acc.x = fmaf(v0, m0.x, fmaf(v1, m1.x, fmaf(v2, m2.x, fmaf(v3, m3.x, acc.x))));
        acc.y = fmaf(v0, m0.y, fmaf(v1, m1.y, fmaf(v2, m2.y, fmaf(v3, m3.y, acc.y))));
        acc.z = fmaf(v0, m0.z, fmaf(v1, m1.z, fmaf(v2, m2.z, fmaf(v3, m3.z, acc.z))));
        acc.w = fmaf(v0, m0.w, fmaf(v1, m1.w, fmaf(v2, m2.w, fmaf(v3, m3.w, acc.w))));
    }
    for (; i < e; i++) {
        const int2 p = g_epack[i];
        const float v = __int_as_float(p.y);
        const float4 m = __ldg(reinterpret_cast<const float4*>(&g_xw[(size_t)p.x * D_OUT + coff]));
        acc.x = fmaf(v, m.x, acc.x);
        acc.y = fmaf(v, m.y, acc.y);
        acc.z = fmaf(v, m.z, acc.z);
        acc.w = fmaf(v, m.w, acc.w);
    }

    const float4 b = *reinterpret_cast<const float4*>(&bias[coff]);
    acc.x = fmaxf(acc.x + b.x, 0.f);
    acc.y = fmaxf(acc.y + b.y, 0.f);
    acc.z = fmaxf(acc.z + b.z, 0.f);
    acc.w = fmaxf(acc.w + b.w, 0.f);

    *reinterpret_cast<float4*>(&out[(size_t)row * D_OUT + coff]) = acc;
}

// ---------------------------------------------------------------------------
// Launch: CSR build on a side stream, GEMM on the main stream, join, SpMM.
// Stream/events are created once, lazily, outside graph capture (the harness
// runs a correctness call before capturing). No device memory is allocated.
// ---------------------------------------------------------------------------
static cudaStream_t g_side  = nullptr;
static cudaEvent_t  g_fork  = nullptr;
static cudaEvent_t  g_join  = nullptr;

extern "C" void kernel_launch(void* const* d_in, const int* in_sizes, int n_in,
                              void* d_out, int out_size)
{
    const float* x         = (const float*)d_in[0];
    const int*   edge_row  = (const int*)  d_in[1];
    const int*   edge_col  = (const int*)  d_in[2];
    const float* edge_vals = (const float*)d_in[3];
    const float* weight    = (const float*)d_in[4];
    const float* bias      = (const float*)d_in[5];
    float* out = (float*)d_out;

    if (g_side == nullptr) {
        cudaStreamCreateWithFlags(&g_side, cudaStreamNonBlocking);
        cudaEventCreateWithFlags(&g_fork, cudaEventDisableTiming);
        cudaEventCreateWithFlags(&g_join, cudaEventDisableTiming);
    }

    // Fork side stream off the launch stream
    cudaEventRecord(g_fork, 0);
    cudaStreamWaitEvent(g_side, g_fork, 0);

    // Side branch: CSR build
    zero_counts_kernel<<<(N_NODES + 255) / 256, 256, 0, g_side>>>();
    count_kernel<<<(N_EDGES + 255) / 256, 256, 0, g_side>>>(edge_row);
    scan_kernel<<<1, 1024, 0, g_side>>>();
    fill_kernel<<<(N_EDGES + 255) / 256, 256, 0, g_side>>>(edge_row, edge_col, edge_vals);
    cudaEventRecord(g_join, g_side);

    // Main branch: GEMM (runs concurrently with CSR build)
    dim3 gemm_grid((N_NODES + GBM - 1) / GBM, D_OUT / GBN);
    gemm_xw_kernel<<<gemm_grid, 256>>>(x, weight);

    // Join, then SpMM + bias + relu
    cudaStreamWaitEvent(0, g_join, 0);
    int n_warps  = N_NODES * 2;
    int n_blocks = (n_warps * 32 + 255) / 256;
    spmm_kernel<<<n_blocks, 256>>>(bias, out);
}